// round 6
// baseline (speedup 1.0000x reference)
#include <cuda_runtime.h>
#include <cuda_bf16.h>

// V[b,n,f,t] = sum_p cos(obs[b,p,f,t] - tpd[b,p,n,f])
// 4-mic square degeneracy: pairs[3]==pairs[2], pairs[5]==-pairs[0] ->
// rank-8 contraction over 4 distinct phase groups (rep pairs 0,1,2,4):
//   V = uc0*c0 + us0*s0 + uc1*c1 + us1*s1 + uc2*c2 + us2*s2 + uc3*c3 + us3*s3
//
// B=4, P=6, N=36, F=257, T=300. One block of 320 threads per (b,f).
// Phase 1 (tid<144): steering sincos -> smem cs[36][8].
// Phase 2 (tid<300): thread = (n-half, t-pair). 12 sincos -> 16 combined
// regs, then 18 n-iters of (2 LDS.128 + 16 FFMA + 1 STG.64).
// Low register budget (launch_bounds 320,5) -> ~78% occupancy cap.

#define NP    6
#define NG    4
#define NDIR  36
#define NF    257
#define NT    300
#define NB    4
#define NTP   150          // t-pairs
#define NH    2            // n-halves
#define NPH   18           // n per half

__global__ __launch_bounds__(320, 5)
void dirfeat_kernel(const float* __restrict__ obs,     // (B*P, F, T)
                    const float* __restrict__ azi,     // (B, N)
                    const float* __restrict__ ele,     // (B, N)
                    const float* __restrict__ pairs,   // (P, 3)
                    const float* __restrict__ freq,    // (F,)
                    float* __restrict__ out)           // (B, N, F, T)
{
    const int b  = blockIdx.x / NF;
    const int f  = blockIdx.x - b * NF;
    const int tid = threadIdx.x;

    // cs[n][2g] = cos(tau_g), cs[n][2g+1] = sin(tau_g)
    __shared__ __align__(16) float cs[NDIR][2 * NG];

    // ---- Phase 1: 144 steering entries ----
    if (tid < NDIR * NG) {
        const int n = tid >> 2;
        const int g = tid & 3;
        const int rep = (g == 3) ? 4 : g;   // rep pair indices {0,1,2,4}

        const float a  = azi[b * NDIR + n];
        const float el = ele[b * NDIR + n];
        float sa, ca, se, ce;
        __sincosf(a,  &sa, &ca);
        __sincosf(el, &se, &ce);
        const float rx = se * ca, ry = se * sa, rz = ce;
        const float dot = pairs[rep * 3 + 0] * rx
                        + pairs[rep * 3 + 1] * ry
                        + pairs[rep * 3 + 2] * rz;
        const float tau = (6.283185307179586f / 343.0f) * dot * freq[f];
        float s, c;
        __sincosf(tau, &s, &c);
        cs[n][2 * g]     = c;
        cs[n][2 * g + 1] = s;
    }
    __syncthreads();

    // ---- Phase 2: threads 0..299 -> (n-half, t-pair) ----
    if (tid < NH * NTP) {
        const int h  = (tid >= NTP) ? 1 : 0;
        const int tp = tid - h * NTP;
        const int t0 = tp * 2;

        const int pstr = NF * NT;
        const float* ob = obs + ((b * NP) * NF + f) * NT + t0;

        // Combined obs terms for the 2 t's: uc{g}{x,y}, us{g}{x,y}
        float uc0x, uc0y, us0x, us0y;
        float uc1x, uc1y, us1x, us1y;
        float uc2x, uc2y, us2x, us2y;
        float uc3x, uc3y, us3x, us3y;

        {   // group 0: pairs 0 and 5 (negated vector -> sin difference)
            const float2 oA = *reinterpret_cast<const float2*>(ob + 0 * pstr);
            const float2 oB = *reinterpret_cast<const float2*>(ob + 5 * pstr);
            float sA, cA, sB, cB;
            __sincosf(oA.x, &sA, &cA); __sincosf(oB.x, &sB, &cB);
            uc0x = cA + cB; us0x = sA - sB;
            __sincosf(oA.y, &sA, &cA); __sincosf(oB.y, &sB, &cB);
            uc0y = cA + cB; us0y = sA - sB;
        }
        {   // group 1: pair 1 alone
            const float2 o = *reinterpret_cast<const float2*>(ob + 1 * pstr);
            __sincosf(o.x, &us1x, &uc1x);
            __sincosf(o.y, &us1y, &uc1y);
        }
        {   // group 2: pairs 2 and 3 (identical vector -> sum)
            const float2 oA = *reinterpret_cast<const float2*>(ob + 2 * pstr);
            const float2 oB = *reinterpret_cast<const float2*>(ob + 3 * pstr);
            float sA, cA, sB, cB;
            __sincosf(oA.x, &sA, &cA); __sincosf(oB.x, &sB, &cB);
            uc2x = cA + cB; us2x = sA + sB;
            __sincosf(oA.y, &sA, &cA); __sincosf(oB.y, &sB, &cB);
            uc2y = cA + cB; us2y = sA + sB;
        }
        {   // group 3: pair 4 alone
            const float2 o = *reinterpret_cast<const float2*>(ob + 4 * pstr);
            __sincosf(o.x, &us3x, &uc3x);
            __sincosf(o.y, &us3y, &uc3y);
        }

        const int nstride = NF * NT;
        float* outp = out + (((b * NDIR + h * NPH) * NF + f)) * NT + t0;
        const float4* cp = reinterpret_cast<const float4*>(&cs[h * NPH][0]);

#pragma unroll
        for (int i = 0; i < NPH; i++) {
            const float4 w0 = cp[2 * i];       // c0 s0 c1 s1
            const float4 w1 = cp[2 * i + 1];   // c2 s2 c3 s3

            float a0 = uc0x * w0.x;
            float a1 = uc0y * w0.x;
            a0 = fmaf(us0x, w0.y, a0);  a1 = fmaf(us0y, w0.y, a1);
            a0 = fmaf(uc1x, w0.z, a0);  a1 = fmaf(uc1y, w0.z, a1);
            a0 = fmaf(us1x, w0.w, a0);  a1 = fmaf(us1y, w0.w, a1);
            a0 = fmaf(uc2x, w1.x, a0);  a1 = fmaf(uc2y, w1.x, a1);
            a0 = fmaf(us2x, w1.y, a0);  a1 = fmaf(us2y, w1.y, a1);
            a0 = fmaf(uc3x, w1.z, a0);  a1 = fmaf(uc3y, w1.z, a1);
            a0 = fmaf(us3x, w1.w, a0);  a1 = fmaf(us3y, w1.w, a1);

            *reinterpret_cast<float2*>(outp + i * nstride) = make_float2(a0, a1);
        }
    }
}

extern "C" void kernel_launch(void* const* d_in, const int* in_sizes, int n_in,
                              void* d_out, int out_size) {
    const float* obs   = (const float*)d_in[0];
    const float* azi   = (const float*)d_in[1];
    const float* ele   = (const float*)d_in[2];
    const float* pairs = (const float*)d_in[3];
    const float* freq  = (const float*)d_in[4];
    float* out = (float*)d_out;

    dim3 grid(NB * NF);   // 1028 blocks: one per (b,f)
    dim3 block(320);      // 10 warps, 300 active in phase 2
    dirfeat_kernel<<<grid, block>>>(obs, azi, ele, pairs, freq, out);
}

// round 7
// speedup vs baseline: 1.4915x; 1.4915x over previous
#include <cuda_runtime.h>
#include <cuda_bf16.h>

// V[b,n,f,t] = sum_p cos(obs[b,p,f,t] - tpd[b,p,n,f])
// 4-mic square degeneracy: pairs[3]==pairs[2], pairs[5]==-pairs[0] ->
// rank-8 contraction over 4 distinct phase groups (rep pairs 0,1,2,4):
//   V = uc0*c0 + us0*s0 + uc1*c1 + us1*s1 + uc2*c2 + us2*s2 + uc3*c3 + us3*s3
//
// B=4, P=6, N=36, F=257, T=300. One block of 160 threads per (b,f).
// Phase 1 (tid<144): steering sincos -> smem cs[36][8].
// Phase 2 (tid<150): thread = (n-half, t-quad); float4 obs loads, 24 sincos
// -> 32 combined regs, then 18 n-iters of (2 LDS.128 + 32 FFMA + 1 STG.128).
// 32-bit indexing + launch_bounds(160,7) to push residency to 7 blocks/SM.

#define NP    6
#define NG    4
#define NDIR  36
#define NF    257
#define NT    300
#define NB    4
#define NTQ   75           // t-quads
#define NH    2            // n-halves
#define NPH   18           // n per half

__global__ __launch_bounds__(160, 7)
void dirfeat_kernel(const float* __restrict__ obs,     // (B*P, F, T)
                    const float* __restrict__ azi,     // (B, N)
                    const float* __restrict__ ele,     // (B, N)
                    const float* __restrict__ pairs,   // (P, 3)
                    const float* __restrict__ freq,    // (F,)
                    float* __restrict__ out)           // (B, N, F, T)
{
    const int b  = blockIdx.x / NF;
    const int f  = blockIdx.x - b * NF;
    const int tid = threadIdx.x;

    // cs[n][2g] = cos(tau_g), cs[n][2g+1] = sin(tau_g)
    __shared__ __align__(16) float cs[NDIR][2 * NG];

    // ---- Phase 1: 144 steering entries ----
    if (tid < NDIR * NG) {
        const int n = tid >> 2;
        const int g = tid & 3;
        const int rep = (g == 3) ? 4 : g;   // rep pair indices {0,1,2,4}

        const float a  = azi[b * NDIR + n];
        const float el = ele[b * NDIR + n];
        float sa, ca, se, ce;
        __sincosf(a,  &sa, &ca);
        __sincosf(el, &se, &ce);
        const float rx = se * ca, ry = se * sa, rz = ce;
        const float dot = pairs[rep * 3 + 0] * rx
                        + pairs[rep * 3 + 1] * ry
                        + pairs[rep * 3 + 2] * rz;
        const float tau = (6.283185307179586f / 343.0f) * dot * freq[f];
        float s, c;
        __sincosf(tau, &s, &c);
        cs[n][2 * g]     = c;
        cs[n][2 * g + 1] = s;
    }
    __syncthreads();

    // ---- Phase 2: threads 0..149 -> (n-half, t-quad) ----
    if (tid < NH * NTQ) {
        const int h  = (tid >= NTQ) ? 1 : 0;
        const int tq = tid - h * NTQ;
        const int t0 = tq * 4;

        const unsigned pstr = NF * NT;                 // 77100
        const float* ob = obs + (unsigned)((b * NP) * NF + f) * NT + t0;

        float uc[NG][4], us[NG][4];

        {   // group 0: pairs 0 and 5 (negated vector -> sin difference)
            const float4 oA = *reinterpret_cast<const float4*>(ob);
            const float4 oB = *reinterpret_cast<const float4*>(ob + 5 * pstr);
            float sA, cA, sB, cB;
            __sincosf(oA.x, &sA, &cA); __sincosf(oB.x, &sB, &cB);
            uc[0][0] = cA + cB; us[0][0] = sA - sB;
            __sincosf(oA.y, &sA, &cA); __sincosf(oB.y, &sB, &cB);
            uc[0][1] = cA + cB; us[0][1] = sA - sB;
            __sincosf(oA.z, &sA, &cA); __sincosf(oB.z, &sB, &cB);
            uc[0][2] = cA + cB; us[0][2] = sA - sB;
            __sincosf(oA.w, &sA, &cA); __sincosf(oB.w, &sB, &cB);
            uc[0][3] = cA + cB; us[0][3] = sA - sB;
        }
        {   // group 2: pairs 2 and 3 (identical vector -> sum)
            const float4 oA = *reinterpret_cast<const float4*>(ob + 2 * pstr);
            const float4 oB = *reinterpret_cast<const float4*>(ob + 3 * pstr);
            float sA, cA, sB, cB;
            __sincosf(oA.x, &sA, &cA); __sincosf(oB.x, &sB, &cB);
            uc[2][0] = cA + cB; us[2][0] = sA + sB;
            __sincosf(oA.y, &sA, &cA); __sincosf(oB.y, &sB, &cB);
            uc[2][1] = cA + cB; us[2][1] = sA + sB;
            __sincosf(oA.z, &sA, &cA); __sincosf(oB.z, &sB, &cB);
            uc[2][2] = cA + cB; us[2][2] = sA + sB;
            __sincosf(oA.w, &sA, &cA); __sincosf(oB.w, &sB, &cB);
            uc[2][3] = cA + cB; us[2][3] = sA + sB;
        }
        {   // group 1: pair 1 alone
            const float4 o = *reinterpret_cast<const float4*>(ob + 1 * pstr);
            __sincosf(o.x, &us[1][0], &uc[1][0]);
            __sincosf(o.y, &us[1][1], &uc[1][1]);
            __sincosf(o.z, &us[1][2], &uc[1][2]);
            __sincosf(o.w, &us[1][3], &uc[1][3]);
        }
        {   // group 3: pair 4 alone
            const float4 o = *reinterpret_cast<const float4*>(ob + 4 * pstr);
            __sincosf(o.x, &us[3][0], &uc[3][0]);
            __sincosf(o.y, &us[3][1], &uc[3][1]);
            __sincosf(o.z, &us[3][2], &uc[3][2]);
            __sincosf(o.w, &us[3][3], &uc[3][3]);
        }

        const unsigned nstride = NF * NT;
        float* outp = out + (unsigned)((b * NDIR + h * NPH) * NF + f) * NT + t0;
        const float4* cp = reinterpret_cast<const float4*>(&cs[h * NPH][0]);

#pragma unroll
        for (int i = 0; i < NPH; i++) {
            const float4 w0 = cp[2 * i];       // c0 s0 c1 s1
            const float4 w1 = cp[2 * i + 1];   // c2 s2 c3 s3

            float a0, a1, a2, a3;
            a0 = uc[0][0] * w0.x;               a1 = uc[0][1] * w0.x;
            a2 = uc[0][2] * w0.x;               a3 = uc[0][3] * w0.x;
            a0 = fmaf(us[0][0], w0.y, a0);      a1 = fmaf(us[0][1], w0.y, a1);
            a2 = fmaf(us[0][2], w0.y, a2);      a3 = fmaf(us[0][3], w0.y, a3);
            a0 = fmaf(uc[1][0], w0.z, a0);      a1 = fmaf(uc[1][1], w0.z, a1);
            a2 = fmaf(uc[1][2], w0.z, a2);      a3 = fmaf(uc[1][3], w0.z, a3);
            a0 = fmaf(us[1][0], w0.w, a0);      a1 = fmaf(us[1][1], w0.w, a1);
            a2 = fmaf(us[1][2], w0.w, a2);      a3 = fmaf(us[1][3], w0.w, a3);
            a0 = fmaf(uc[2][0], w1.x, a0);      a1 = fmaf(uc[2][1], w1.x, a1);
            a2 = fmaf(uc[2][2], w1.x, a2);      a3 = fmaf(uc[2][3], w1.x, a3);
            a0 = fmaf(us[2][0], w1.y, a0);      a1 = fmaf(us[2][1], w1.y, a1);
            a2 = fmaf(us[2][2], w1.y, a2);      a3 = fmaf(us[2][3], w1.y, a3);
            a0 = fmaf(uc[3][0], w1.z, a0);      a1 = fmaf(uc[3][1], w1.z, a1);
            a2 = fmaf(uc[3][2], w1.z, a2);      a3 = fmaf(uc[3][3], w1.z, a3);
            a0 = fmaf(us[3][0], w1.w, a0);      a1 = fmaf(us[3][1], w1.w, a1);
            a2 = fmaf(us[3][2], w1.w, a2);      a3 = fmaf(us[3][3], w1.w, a3);

            *reinterpret_cast<float4*>(outp + i * nstride) =
                make_float4(a0, a1, a2, a3);
        }
    }
}

extern "C" void kernel_launch(void* const* d_in, const int* in_sizes, int n_in,
                              void* d_out, int out_size) {
    const float* obs   = (const float*)d_in[0];
    const float* azi   = (const float*)d_in[1];
    const float* ele   = (const float*)d_in[2];
    const float* pairs = (const float*)d_in[3];
    const float* freq  = (const float*)d_in[4];
    float* out = (float*)d_out;

    dim3 grid(NB * NF);   // 1028 blocks: one per (b,f)
    dim3 block(160);      // 5 warps, 150 active in phase 2
    dirfeat_kernel<<<grid, block>>>(obs, azi, ele, pairs, freq, out);
}

// round 8
// speedup vs baseline: 1.7098x; 1.1463x over previous
#include <cuda_runtime.h>
#include <cuda_bf16.h>
#include <cstdint>

// V[b,n,f,t] = sum_p cos(obs[b,p,f,t] - tpd[b,p,n,f])
// 4-mic square degeneracy: pairs[3]==pairs[2], pairs[5]==-pairs[0] ->
// rank-8 contraction over 4 distinct phase groups (rep pairs 0,1,2,4).
//
// Round-8: packed f32x2 inner loop. Accumulators pack t-pairs
// ({V[n,t0],V[n,t1]}, {V[n,t2],V[n,t3]}), obs terms packed once per thread,
// steering coeffs stored DUPLICATED in smem ({w,w}) so the per-n broadcast
// is a single LDS.64. Store via st.global.v2.u64 (16B).
// Per n: 8 LDS.64 + 16 FFMA2 + 1 STG.128  (was 2 LDS + 32 FFMA + 1 STG).

#define NP    6
#define NG    4
#define NDIR  36
#define NF    257
#define NT    300
#define NB    4
#define NTQ   75           // t-quads
#define NH    2            // n-halves
#define NPH   18           // n per half

#define MUL2(d, a, b) asm("mul.rn.f32x2 %0, %1, %2;" : "=l"(d) : "l"(a), "l"(b))
#define FMA2(d, a, b) asm("fma.rn.f32x2 %0, %1, %2, %0;" : "+l"(d) : "l"(a), "l"(b))
#define STG_V2U64(p, x, y) \
    asm volatile("st.global.v2.u64 [%0], {%1, %2};" :: "l"(p), "l"(x), "l"(y) : "memory")

__device__ __forceinline__ unsigned long long pack2(float lo, float hi) {
    unsigned long long r;
    asm("mov.b64 %0, {%1, %2};" : "=l"(r) : "f"(lo), "f"(hi));
    return r;
}

__global__ __launch_bounds__(160)
void dirfeat_kernel(const float* __restrict__ obs,     // (B*P, F, T)
                    const float* __restrict__ azi,     // (B, N)
                    const float* __restrict__ ele,     // (B, N)
                    const float* __restrict__ pairs,   // (P, 3)
                    const float* __restrict__ freq,    // (F,)
                    float* __restrict__ out)           // (B, N, F, T)
{
    const int b  = blockIdx.x / NF;
    const int f  = blockIdx.x - b * NF;
    const int tid = threadIdx.x;

    // csD[n][plane][dup] ; planes: uc0,us0,uc1,us1,uc2,us2,uc3,us3 (duplicated)
    __shared__ __align__(16) float csD[NDIR][8][2];

    // ---- Phase 1: 144 steering entries ----
    if (tid < NDIR * NG) {
        const int n = tid >> 2;
        const int g = tid & 3;
        const int rep = (g == 3) ? 4 : g;   // rep pair indices {0,1,2,4}

        const float a  = azi[b * NDIR + n];
        const float el = ele[b * NDIR + n];
        float sa, ca, se, ce;
        __sincosf(a,  &sa, &ca);
        __sincosf(el, &se, &ce);
        const float rx = se * ca, ry = se * sa, rz = ce;
        const float dot = pairs[rep * 3 + 0] * rx
                        + pairs[rep * 3 + 1] * ry
                        + pairs[rep * 3 + 2] * rz;
        const float tau = (6.283185307179586f / 343.0f) * dot * freq[f];
        float s, c;
        __sincosf(tau, &s, &c);
        csD[n][2 * g][0]     = c;  csD[n][2 * g][1]     = c;
        csD[n][2 * g + 1][0] = s;  csD[n][2 * g + 1][1] = s;
    }
    __syncthreads();

    // ---- Phase 2: threads 0..149 -> (n-half, t-quad) ----
    if (tid < NH * NTQ) {
        const int h  = (tid >= NTQ) ? 1 : 0;
        const int tq = tid - h * NTQ;
        const int t0 = tq * 4;

        const unsigned pstr = NF * NT;                 // 77100
        const float* ob = obs + (unsigned)((b * NP) * NF + f) * NT + t0;

        float uc[NG][4], us[NG][4];

        {   // group 0: pairs 0 and 5 (negated vector -> sin difference)
            const float4 oA = *reinterpret_cast<const float4*>(ob);
            const float4 oB = *reinterpret_cast<const float4*>(ob + 5 * pstr);
            float sA, cA, sB, cB;
            __sincosf(oA.x, &sA, &cA); __sincosf(oB.x, &sB, &cB);
            uc[0][0] = cA + cB; us[0][0] = sA - sB;
            __sincosf(oA.y, &sA, &cA); __sincosf(oB.y, &sB, &cB);
            uc[0][1] = cA + cB; us[0][1] = sA - sB;
            __sincosf(oA.z, &sA, &cA); __sincosf(oB.z, &sB, &cB);
            uc[0][2] = cA + cB; us[0][2] = sA - sB;
            __sincosf(oA.w, &sA, &cA); __sincosf(oB.w, &sB, &cB);
            uc[0][3] = cA + cB; us[0][3] = sA - sB;
        }
        {   // group 2: pairs 2 and 3 (identical vector -> sum)
            const float4 oA = *reinterpret_cast<const float4*>(ob + 2 * pstr);
            const float4 oB = *reinterpret_cast<const float4*>(ob + 3 * pstr);
            float sA, cA, sB, cB;
            __sincosf(oA.x, &sA, &cA); __sincosf(oB.x, &sB, &cB);
            uc[2][0] = cA + cB; us[2][0] = sA + sB;
            __sincosf(oA.y, &sA, &cA); __sincosf(oB.y, &sB, &cB);
            uc[2][1] = cA + cB; us[2][1] = sA + sB;
            __sincosf(oA.z, &sA, &cA); __sincosf(oB.z, &sB, &cB);
            uc[2][2] = cA + cB; us[2][2] = sA + sB;
            __sincosf(oA.w, &sA, &cA); __sincosf(oB.w, &sB, &cB);
            uc[2][3] = cA + cB; us[2][3] = sA + sB;
        }
        {   // group 1: pair 1 alone
            const float4 o = *reinterpret_cast<const float4*>(ob + 1 * pstr);
            __sincosf(o.x, &us[1][0], &uc[1][0]);
            __sincosf(o.y, &us[1][1], &uc[1][1]);
            __sincosf(o.z, &us[1][2], &uc[1][2]);
            __sincosf(o.w, &us[1][3], &uc[1][3]);
        }
        {   // group 3: pair 4 alone
            const float4 o = *reinterpret_cast<const float4*>(ob + 4 * pstr);
            __sincosf(o.x, &us[3][0], &uc[3][0]);
            __sincosf(o.y, &us[3][1], &uc[3][1]);
            __sincosf(o.z, &us[3][2], &uc[3][2]);
            __sincosf(o.w, &us[3][3], &uc[3][3]);
        }

        // Pack obs terms over t-pairs: U[plane][j], j=0 -> {t0,t1}, j=1 -> {t2,t3}
        unsigned long long U[8][2];
#pragma unroll
        for (int g = 0; g < NG; g++) {
            U[2 * g][0]     = pack2(uc[g][0], uc[g][1]);
            U[2 * g][1]     = pack2(uc[g][2], uc[g][3]);
            U[2 * g + 1][0] = pack2(us[g][0], us[g][1]);
            U[2 * g + 1][1] = pack2(us[g][2], us[g][3]);
        }

        const unsigned nstride = NF * NT;
        float* outp = out + (unsigned)((b * NDIR + h * NPH) * NF + f) * NT + t0;

#pragma unroll
        for (int i = 0; i < NPH; i++) {
            const int n = h * NPH + i;
            const unsigned long long* w8 =
                reinterpret_cast<const unsigned long long*>(&csD[n][0][0]);

            unsigned long long w0 = w8[0], w1 = w8[1], w2 = w8[2], w3 = w8[3];
            unsigned long long w4 = w8[4], w5 = w8[5], w6 = w8[6], w7 = w8[7];

            unsigned long long acc01, acc23;
            MUL2(acc01, U[0][0], w0);        MUL2(acc23, U[0][1], w0);
            FMA2(acc01, U[1][0], w1);        FMA2(acc23, U[1][1], w1);
            FMA2(acc01, U[2][0], w2);        FMA2(acc23, U[2][1], w2);
            FMA2(acc01, U[3][0], w3);        FMA2(acc23, U[3][1], w3);
            FMA2(acc01, U[4][0], w4);        FMA2(acc23, U[4][1], w4);
            FMA2(acc01, U[5][0], w5);        FMA2(acc23, U[5][1], w5);
            FMA2(acc01, U[6][0], w6);        FMA2(acc23, U[6][1], w6);
            FMA2(acc01, U[7][0], w7);        FMA2(acc23, U[7][1], w7);

            STG_V2U64(outp + i * nstride, acc01, acc23);
        }
    }
}

extern "C" void kernel_launch(void* const* d_in, const int* in_sizes, int n_in,
                              void* d_out, int out_size) {
    const float* obs   = (const float*)d_in[0];
    const float* azi   = (const float*)d_in[1];
    const float* ele   = (const float*)d_in[2];
    const float* pairs = (const float*)d_in[3];
    const float* freq  = (const float*)d_in[4];
    float* out = (float*)d_out;

    dim3 grid(NB * NF);   // 1028 blocks: one per (b,f)
    dim3 block(160);      // 5 warps, 150 active in phase 2
    dirfeat_kernel<<<grid, block>>>(obs, azi, ele, pairs, freq, out);
}